// round 4
// baseline (speedup 1.0000x reference)
#include <cuda_runtime.h>
#include <cuda_bf16.h>

#define BSZ 8
#define LEN 4096
#define DM  128   // d_model (M)
#define DS  128   // d_state (N)

#define TO 512    // output tile (time) per CTA
#define TU 128    // input tile (time)
#define NT 128    // threads per CTA (conv)

// -------- scratch (__device__ globals; no allocation allowed) --------
__device__ float g_xt[BSZ * DM * LEN];    // x transposed to (b, m, l)  ~16.8MB
__device__ float g_psum[DS * LEN];        // Psum[k, l]                 ~2MB
__device__ float g_kern[DM * LEN];        // kernel[m, l]               ~2MB
__device__ float g_G[DM * DS];            // G = C @ B

// -------- 1) transpose x (b,l,m) -> (b,m,l) --------
__global__ void transpose_kernel(const float* __restrict__ x) {
    __shared__ float tile[32][33];
    int b  = blockIdx.z;
    int l0 = blockIdx.x * 32;
    int m0 = blockIdx.y * 32;
    int tx = threadIdx.x, ty = threadIdx.y;
#pragma unroll
    for (int j = 0; j < 32; j += 8)
        tile[ty + j][tx] = x[(b * LEN + l0 + ty + j) * DM + m0 + tx];
    __syncthreads();
#pragma unroll
    for (int j = 0; j < 32; j += 8)
        g_xt[(b * DM + m0 + ty + j) * LEN + l0 + tx] = tile[tx][ty + j];
}

// -------- 2) Psum[k,l] = sum_{m'} exp(dt[m'] * Lam[k] * l) --------
__global__ void psum_kernel(const float* __restrict__ Lam,
                            const float* __restrict__ log_dt) {
    __shared__ float dt_s[DM];
    int k = blockIdx.x;
    int l = blockIdx.y * 128 + threadIdx.x;
    dt_s[threadIdx.x] = __expf(log_dt[threadIdx.x]);
    __syncthreads();
    float a = Lam[k] * (float)l;   // <= 0
    float s = 0.f;
#pragma unroll 8
    for (int mp = 0; mp < DM; ++mp)
        s += __expf(dt_s[mp] * a);
    g_psum[k * LEN + l] = s;
}

// -------- 3) G = C @ B  (G[m,k] = sum_i C[m,i] * B[i,k]) --------
__global__ void gmat_kernel(const float* __restrict__ Bm,
                            const float* __restrict__ Cm) {
    __shared__ float c_s[DS];
    int m = blockIdx.x;
    int k = threadIdx.x;
    c_s[k] = Cm[m * DS + k];
    __syncthreads();
    float g = 0.f;
#pragma unroll 8
    for (int i = 0; i < DS; ++i)
        g = fmaf(c_s[i], Bm[i * DM + k], g);
    g_G[m * DS + k] = g;
}

// -------- 4) kernel[m,l] = sum_k G[m,k] * Psum[k,l] --------
__global__ void kern_kernel() {
    __shared__ float gs[DS];
    int m = blockIdx.x;
    int l = blockIdx.y * 128 + threadIdx.x;
    gs[threadIdx.x] = g_G[m * DS + threadIdx.x];
    __syncthreads();
    float s = 0.f;
#pragma unroll 8
    for (int k = 0; k < DS; ++k)
        s = fmaf(gs[k], g_psum[k * LEN + l], s);
    g_kern[m * LEN + l] = s;
}

// -------- 5) causal conv + skip:  y[b,l,m] = Dv[m]*x + sum_{j<=l} kern[m,j]*x[b,m,l-j]
// CTA = (time-tile tt, channel m). 128 threads; each thread owns 4 output rows
// (l = t0 + tid + r*128) x 8 batches = 32 fp32 accumulators.
__global__ void __launch_bounds__(NT) conv_kernel(const float* __restrict__ Dv,
                                                  float* __restrict__ out) {
    __shared__ float k_s[TO + TU];   // 640
    __shared__ float x_s[TU * 9];    // pad 9 -> conflict-free

    const int m   = blockIdx.y;
    const int tt  = (int)(gridDim.x - 1 - blockIdx.x);  // heavy tiles first
    const int t0  = tt * TO;
    const int tid = threadIdx.x;

    float acc[4][8];
#pragma unroll
    for (int r = 0; r < 4; ++r)
#pragma unroll
        for (int b = 0; b < 8; ++b) acc[r][b] = 0.f;

    const float* krow = g_kern + m * LEN;
    const int n_u = t0 / TU + TO / TU;   // input tiles covering u <= t0+TO-1

    for (int ut = 0; ut < n_u; ++ut) {
        const int u0 = ut * TU;
        __syncthreads();   // protect smem reuse across iterations
        // kernel segment: j = j0 + i, i in [0, TO+TU)
        const int j0 = t0 - u0 - (TU - 1);
#pragma unroll
        for (int ii = 0; ii < (TO + TU) / NT; ++ii) {
            int i = tid + ii * NT;
            int j = j0 + i;
            k_s[i] = (j >= 0) ? krow[j] : 0.f;
        }
        // x tile: x_s[uj*9 + b] = xt[b, m, u0+uj]; coalesced per b
#pragma unroll
        for (int b = 0; b < 8; ++b)
            x_s[tid * 9 + b] = g_xt[(b * DM + m) * LEN + u0 + tid];
        __syncthreads();

#pragma unroll 4
        for (int uj = 0; uj < TU; ++uj) {
            float xv[8];
#pragma unroll
            for (int b = 0; b < 8; ++b) xv[b] = x_s[uj * 9 + b];
#pragma unroll
            for (int r = 0; r < 4; ++r) {
                float kv = k_s[tid + r * 128 - uj + (TU - 1)];
#pragma unroll
                for (int b = 0; b < 8; ++b)
                    acc[r][b] = fmaf(kv, xv[b], acc[r][b]);
            }
        }
    }

    // epilogue: skip connection + store to (b, l, m)
    const float dv = Dv[m];
#pragma unroll
    for (int r = 0; r < 4; ++r) {
        int l = t0 + tid + r * 128;
#pragma unroll
        for (int b = 0; b < 8; ++b) {
            float xval = g_xt[(b * DM + m) * LEN + l];
            out[(b * LEN + l) * DM + m] = fmaf(dv, xval, acc[r][b]);
        }
    }
}

extern "C" void kernel_launch(void* const* d_in, const int* in_sizes, int n_in,
                              void* d_out, int out_size) {
    const float* x      = (const float*)d_in[0];  // (8, 4096, 128)
    const float* Lam    = (const float*)d_in[1];  // (128,)
    const float* Bm     = (const float*)d_in[2];  // (128, 128)
    const float* Cm     = (const float*)d_in[3];  // (128, 128)
    const float* Dv     = (const float*)d_in[4];  // (128,)
    const float* log_dt = (const float*)d_in[5];  // (128,)
    float* out = (float*)d_out;

    transpose_kernel<<<dim3(LEN / 32, DM / 32, BSZ), dim3(32, 8)>>>(x);
    psum_kernel<<<dim3(DS, LEN / 128), 128>>>(Lam, log_dt);
    gmat_kernel<<<DM, DS>>>(Bm, Cm);
    kern_kernel<<<dim3(DM, LEN / 128), 128>>>();
    conv_kernel<<<dim3(LEN / TO, DM), NT>>>(Dv, out);
}

// round 5
// speedup vs baseline: 1.6318x; 1.6318x over previous
#include <cuda_runtime.h>
#include <cuda_bf16.h>

#define BSZ 8
#define LEN 4096
#define DM  128   // d_model (M)
#define DS  128   // d_state (N)

#define TO 512    // output tile (time) per CTA
#define TU 128    // input tile (time)
#define NT 64     // threads per CTA (conv)
#define RR 8      // output rows (l = t0 + tid + r*64) per thread

// -------- scratch (__device__ globals; no allocation allowed) --------
__device__ float g_xt[BSZ * DM * LEN];    // x transposed to (b, m, l)
__device__ float g_psum[DS * LEN];        // Psum[k, l]
__device__ float g_kern[DM * LEN];        // kernel[m, l]
__device__ float g_G[DM * DS];            // G = C @ B

using u64 = unsigned long long;
__device__ __forceinline__ void ffma2(u64 &d, u64 a, u64 b) {
    asm("fma.rn.f32x2 %0, %1, %2, %0;" : "+l"(d) : "l"(a), "l"(b));
}
__device__ __forceinline__ u64 pack2(float lo, float hi) {
    u64 r; asm("mov.b64 %0, {%1, %2};" : "=l"(r) : "f"(lo), "f"(hi)); return r;
}
__device__ __forceinline__ void unpack2(u64 v, float &lo, float &hi) {
    asm("mov.b64 {%0, %1}, %2;" : "=f"(lo), "=f"(hi) : "l"(v));
}

// -------- 1) transpose x (b,l,m) -> (b,m,l) --------
__global__ void transpose_kernel(const float* __restrict__ x) {
    __shared__ float tile[32][33];
    int b  = blockIdx.z;
    int l0 = blockIdx.x * 32;
    int m0 = blockIdx.y * 32;
    int tx = threadIdx.x, ty = threadIdx.y;
#pragma unroll
    for (int j = 0; j < 32; j += 8)
        tile[ty + j][tx] = x[(b * LEN + l0 + ty + j) * DM + m0 + tx];
    __syncthreads();
#pragma unroll
    for (int j = 0; j < 32; j += 8)
        g_xt[(b * DM + m0 + ty + j) * LEN + l0 + tx] = tile[tx][ty + j];
}

// -------- 2) Psum[k,l] = sum_{m'} exp(dt[m'] * Lam[k] * l) --------
__global__ void psum_kernel(const float* __restrict__ Lam,
                            const float* __restrict__ log_dt) {
    __shared__ float dt_s[DM];
    int k = blockIdx.x;
    int l = blockIdx.y * 128 + threadIdx.x;
    dt_s[threadIdx.x] = __expf(log_dt[threadIdx.x]);
    __syncthreads();
    float a = Lam[k] * (float)l;   // <= 0
    float s = 0.f;
#pragma unroll 8
    for (int mp = 0; mp < DM; ++mp)
        s += __expf(dt_s[mp] * a);
    g_psum[k * LEN + l] = s;
}

// -------- 3) G = C @ B --------
__global__ void gmat_kernel(const float* __restrict__ Bm,
                            const float* __restrict__ Cm) {
    __shared__ float c_s[DS];
    int m = blockIdx.x;
    int k = threadIdx.x;
    c_s[k] = Cm[m * DS + k];
    __syncthreads();
    float g = 0.f;
#pragma unroll 8
    for (int i = 0; i < DS; ++i)
        g = fmaf(c_s[i], Bm[i * DM + k], g);
    g_G[m * DS + k] = g;
}

// -------- 4) kernel[m,l] = sum_k G[m,k] * Psum[k,l], 8 m per CTA --------
__global__ void kern_kernel() {
    __shared__ float gs[8][DS];
    int m0 = blockIdx.x * 8;
    int l  = blockIdx.y * 128 + threadIdx.x;
#pragma unroll
    for (int r = 0; r < 8; ++r)
        gs[r][threadIdx.x] = g_G[(m0 + r) * DS + threadIdx.x];
    __syncthreads();
    float s[8] = {0.f, 0.f, 0.f, 0.f, 0.f, 0.f, 0.f, 0.f};
#pragma unroll 4
    for (int k = 0; k < DS; ++k) {
        float p = g_psum[k * LEN + l];
#pragma unroll
        for (int r = 0; r < 8; ++r)
            s[r] = fmaf(gs[r][k], p, s[r]);
    }
#pragma unroll
    for (int r = 0; r < 8; ++r)
        g_kern[(m0 + r) * LEN + l] = s[r];
}

// -------- 5) causal conv + skip, f32x2 packed FMA --------
// 1D grid of 512: m = bid & 127, tile tt = 3 - bid/128 (heavy tiles on low bids;
// consecutive-bid -> SM placement then mixes all tile weights per SM).
// 64 threads; each owns 8 output rows x 8 batches (packed into 4 f32x2 accs).
__global__ void __launch_bounds__(NT) conv_kernel(const float* __restrict__ Dv,
                                                  float* __restrict__ out) {
    __shared__ __align__(16) float k_s[TO + TU];   // 640
    __shared__ __align__(16) float x_s[TU * 10];   // pad 10 -> 8B-aligned pairs

    const int bid = blockIdx.x;
    const int m   = bid & (DM - 1);
    const int tt  = (LEN / TO - 1) - (bid >> 7);   // 3 - bid/128
    const int t0  = tt * TO;
    const int tid = threadIdx.x;

    u64 acc[RR][4];
#pragma unroll
    for (int r = 0; r < RR; ++r)
#pragma unroll
        for (int h = 0; h < 4; ++h) acc[r][h] = 0ull;

    const float* krow = g_kern + m * LEN;
    const int n_u = (t0 + TO) / TU;

    for (int ut = 0; ut < n_u; ++ut) {
        const int u0 = ut * TU;
        __syncthreads();
        const int j0 = t0 - u0 - (TU - 1);
#pragma unroll
        for (int ii = 0; ii < (TO + TU) / NT; ++ii) {   // 10
            int i = tid + ii * NT;
            int j = j0 + i;
            k_s[i] = (j >= 0 && j < LEN) ? krow[j] : 0.f;
        }
#pragma unroll
        for (int q = 0; q < TU / NT; ++q) {             // 2
            int u = tid + q * NT;
            const float* xp = g_xt + m * LEN + u0 + u;
#pragma unroll
            for (int b = 0; b < BSZ; ++b)
                x_s[u * 10 + b] = xp[b * DM * LEN];
        }
        __syncthreads();

#pragma unroll 2
        for (int uj = 0; uj < TU; ++uj) {
            u64 xv[4];
            const float2* xp2 = (const float2*)(x_s + uj * 10);
#pragma unroll
            for (int h = 0; h < 4; ++h) {
                float2 v = xp2[h];
                xv[h] = pack2(v.x, v.y);
            }
#pragma unroll
            for (int r = 0; r < RR; ++r) {
                float kf = k_s[tid + r * 64 + (TU - 1) - uj];
                u64 kv = pack2(kf, kf);
#pragma unroll
                for (int h = 0; h < 4; ++h)
                    ffma2(acc[r][h], kv, xv[h]);
            }
        }
    }

    // epilogue: skip connection + store to (b, l, m)
    const float dv = Dv[m];
#pragma unroll
    for (int r = 0; r < RR; ++r) {
        int l = t0 + tid + r * 64;
#pragma unroll
        for (int h = 0; h < 4; ++h) {
            float lo, hi;
            unpack2(acc[r][h], lo, hi);
            int b0 = 2 * h, b1 = 2 * h + 1;
            float x0 = g_xt[(b0 * DM + m) * LEN + l];
            float x1 = g_xt[(b1 * DM + m) * LEN + l];
            out[(b0 * LEN + l) * DM + m] = fmaf(dv, x0, lo);
            out[(b1 * LEN + l) * DM + m] = fmaf(dv, x1, hi);
        }
    }
}

extern "C" void kernel_launch(void* const* d_in, const int* in_sizes, int n_in,
                              void* d_out, int out_size) {
    const float* x      = (const float*)d_in[0];  // (8, 4096, 128)
    const float* Lam    = (const float*)d_in[1];  // (128,)
    const float* Bm     = (const float*)d_in[2];  // (128, 128)
    const float* Cm     = (const float*)d_in[3];  // (128, 128)
    const float* Dv     = (const float*)d_in[4];  // (128,)
    const float* log_dt = (const float*)d_in[5];  // (128,)
    float* out = (float*)d_out;

    transpose_kernel<<<dim3(LEN / 32, DM / 32, BSZ), dim3(32, 8)>>>(x);
    psum_kernel<<<dim3(DS, LEN / 128), 128>>>(Lam, log_dt);
    gmat_kernel<<<DM, DS>>>(Bm, Cm);
    kern_kernel<<<dim3(DM / 8, LEN / 128), 128>>>();
    conv_kernel<<<(LEN / TO) * DM, NT>>>(Dv, out);
}